// round 2
// baseline (speedup 1.0000x reference)
#include <cuda_runtime.h>
#include <cuda_bf16.h>
#include <cstdint>

// BitLinear via exact integer math on IMMA (mma.sync m16n8k32 s8):
//   xi = round(x/gamma*127) in [-127,127]  (s8, exact)
//   t  = clip(round(w/alpha),-1,1)         (s8 trit, exact)
//   out[m,n] = gamma[m]*alpha/127 * sum_k xi[m,k]*t[n,k]   (s32 accum, exact)

#define TOKENS 8192
#define KDIM   4096
#define NDIM   16384

// -------- scratch (device globals) --------
__device__ int8_t g_xq[(size_t)TOKENS * KDIM];   // 32 MB
__device__ int8_t g_wq[(size_t)NDIM * KDIM];     // 64 MB
__device__ float  g_gamma[TOKENS];
__device__ float  g_alpha;
__device__ double g_part[1024];

// ---------------- helpers ----------------
__device__ __forceinline__ uint32_t smem_u32(const void* p) {
    uint32_t a;
    asm("{ .reg .u64 t; cvta.to.shared.u64 t, %1; cvt.u32.u64 %0, t; }"
        : "=r"(a) : "l"(p));
    return a;
}

#define SWZ128(o) ((o) ^ (((o) >> 3) & 0x70))

__device__ __forceinline__ void cp_async16(uint32_t dst, const void* src) {
    asm volatile("cp.async.cg.shared.global [%0], [%1], 16;\n"
                 :: "r"(dst), "l"(src));
}
#define CP_COMMIT() asm volatile("cp.async.commit_group;\n" ::: "memory")
#define CP_WAIT(n)  asm volatile("cp.async.wait_group %0;\n" :: "n"(n) : "memory")

__device__ __forceinline__ void ldsm4(uint32_t& r0, uint32_t& r1, uint32_t& r2,
                                      uint32_t& r3, uint32_t addr) {
    asm volatile("ldmatrix.sync.aligned.m8n8.x4.shared.b16 {%0,%1,%2,%3}, [%4];"
                 : "=r"(r0), "=r"(r1), "=r"(r2), "=r"(r3) : "r"(addr));
}

__device__ __forceinline__ void imma(int* c, const uint32_t* a, const uint32_t* b) {
    asm volatile(
        "mma.sync.aligned.m16n8k32.row.col.s32.s8.s8.s32 "
        "{%0,%1,%2,%3}, {%4,%5,%6,%7}, {%8,%9}, {%0,%1,%2,%3};"
        : "+r"(c[0]), "+r"(c[1]), "+r"(c[2]), "+r"(c[3])
        : "r"(a[0]), "r"(a[1]), "r"(a[2]), "r"(a[3]), "r"(b[0]), "r"(b[1]));
}

// ---------------- GEMM config ----------------
#define BM 128
#define BN 128
#define BK 128
#define STAGES 3
#define KTILES (KDIM / BK)            // 32
#define A_STAGE (BM * BK)             // 16384 B
#define B_STAGE (BN * BK)             // 16384 B
#define SM_A_OFF 0
#define SM_B_OFF (STAGES * A_STAGE)   // 49152
#define SM_TOTAL (SM_B_OFF + STAGES * B_STAGE)   // 98304

// Load one (A,B) K-tile stage into swizzled SMEM (256 threads).
__device__ __forceinline__ void load_stage(uint32_t sb, int tid, int m0, int n0,
                                           int kt, int s) {
    const int8_t* abase = g_xq + (size_t)m0 * KDIM + (size_t)kt * BK;
    uint32_t asm_ = sb + SM_A_OFF + s * A_STAGE;
#pragma unroll
    for (int i = 0; i < 4; i++) {                 // 128 rows x 8 chunks(16B)
        int idx = tid + i * 256;
        int r = idx >> 3, ch = idx & 7;
        cp_async16(asm_ + SWZ128(r * 128 + ch * 16),
                   abase + (size_t)r * KDIM + ch * 16);
    }
    const int8_t* bbase = g_wq + (size_t)n0 * KDIM + (size_t)kt * BK;
    uint32_t bsm = sb + SM_B_OFF + s * B_STAGE;
#pragma unroll
    for (int i = 0; i < 4; i++) {
        int idx = tid + i * 256;
        int r = idx >> 3, ch = idx & 7;
        cp_async16(bsm + SWZ128(r * 128 + ch * 16),
                   bbase + (size_t)r * KDIM + ch * 16);
    }
}

__global__ void __launch_bounds__(256, 1) k_gemm(float* __restrict__ out) {
    extern __shared__ __align__(1024) char smem[];
    uint32_t sb = smem_u32(smem);
    int tid = threadIdx.x, wid = tid >> 5, lane = tid & 31;
    int wm = wid & 1, wn = wid >> 1;              // warp grid 2(m) x 4(n)

    // supertile swizzle for L2 reuse
    int bid = blockIdx.x;
    const int TN = NDIM / BN;                     // 128
    const int GRP = 8;
    int g  = bid / (GRP * TN);
    int pm = g * GRP + (bid % GRP);
    int pn = (bid % (GRP * TN)) / GRP;
    int m0 = pm * BM, n0 = pn * BN;

    int acc[4][4][4];                             // [m-frag][n-frag][4]
#pragma unroll
    for (int i = 0; i < 4; i++)
#pragma unroll
        for (int j = 0; j < 4; j++)
#pragma unroll
            for (int q = 0; q < 4; q++) acc[i][j][q] = 0;

    // prologue
#pragma unroll
    for (int s = 0; s < STAGES - 1; s++) {
        load_stage(sb, tid, m0, n0, s, s);
        CP_COMMIT();
    }

    int rlo = lane & 7, sel = lane >> 3;

#pragma unroll 1
    for (int kt = 0; kt < KTILES; kt++) {
        int s = kt % STAGES;
        CP_WAIT(STAGES - 2);
        __syncthreads();

        int kn = kt + STAGES - 1;
        if (kn < KTILES) load_stage(sb, tid, m0, n0, kn, kn % STAGES);
        CP_COMMIT();

        uint32_t a_s = sb + SM_A_OFF + s * A_STAGE;
        uint32_t b_s = sb + SM_B_OFF + s * B_STAGE;
#pragma unroll
        for (int ks = 0; ks < 4; ks++) {          // 4 x k32 per BK=128
            uint32_t af[4][4], bf[4][2];
            // A frags: rows wm*64 + i*16 + (sel&1)*8 + rlo, chunk ks*2+(sel>>1)
#pragma unroll
            for (int i = 0; i < 4; i++) {
                int row = wm * 64 + i * 16 + (sel & 1) * 8 + rlo;
                int ch  = ks * 2 + (sel >> 1);
                ldsm4(af[i][0], af[i][1], af[i][2], af[i][3],
                      a_s + SWZ128(row * 128 + ch * 16));
            }
            // B frag pairs: rows wn*32 + j2*16 + (sel>>1)*8 + rlo, chunk ks*2+(sel&1)
#pragma unroll
            for (int j2 = 0; j2 < 2; j2++) {
                int row = wn * 32 + j2 * 16 + (sel >> 1) * 8 + rlo;
                int ch  = ks * 2 + (sel & 1);
                ldsm4(bf[2 * j2][0], bf[2 * j2][1], bf[2 * j2 + 1][0],
                      bf[2 * j2 + 1][1], b_s + SWZ128(row * 128 + ch * 16));
            }
#pragma unroll
            for (int i = 0; i < 4; i++)
#pragma unroll
                for (int j = 0; j < 4; j++) imma(acc[i][j], af[i], bf[j]);
        }
    }

    // epilogue: out = acc * gamma[row]*alpha/127
    float aod = g_alpha * (1.0f / 127.0f);
    int qrow = lane >> 2, qcol = (lane & 3) * 2;
#pragma unroll
    for (int i = 0; i < 4; i++) {
        int r0 = m0 + wm * 64 + i * 16 + qrow;
        float s0 = g_gamma[r0] * aod;
        float s1 = g_gamma[r0 + 8] * aod;
        float* p0 = out + (size_t)r0 * NDIM + n0 + wn * 32 + qcol;
        float* p1 = p0 + (size_t)8 * NDIM;
#pragma unroll
        for (int j = 0; j < 4; j++) {
            float2 v0 = make_float2((float)acc[i][j][0] * s0,
                                    (float)acc[i][j][1] * s0);
            float2 v1 = make_float2((float)acc[i][j][2] * s1,
                                    (float)acc[i][j][3] * s1);
            *reinterpret_cast<float2*>(p0 + j * 8) = v0;
            *reinterpret_cast<float2*>(p1 + j * 8) = v1;
        }
    }
}

// ---------------- preprocessing ----------------

// deterministic 2-stage |w| mean (double accumulation)
__global__ void k_wabs1(const float4* __restrict__ w) {
    __shared__ double red[256];
    int tid = threadIdx.x;
    size_t base = (size_t)blockIdx.x * 16384;
    double s = 0.0;
    for (int i = tid; i < 16384; i += 256) {
        float4 v = w[base + i];
        s += (double)fabsf(v.x) + (double)fabsf(v.y) +
             (double)fabsf(v.z) + (double)fabsf(v.w);
    }
    red[tid] = s;
    __syncthreads();
    for (int st = 128; st > 0; st >>= 1) {
        if (tid < st) red[tid] += red[tid + st];
        __syncthreads();
    }
    if (tid == 0) g_part[blockIdx.x] = red[0];
}

__global__ void k_wabs2() {
    __shared__ double red[256];
    int tid = threadIdx.x;
    double s = g_part[tid] + g_part[tid + 256] + g_part[tid + 512] + g_part[tid + 768];
    red[tid] = s;
    __syncthreads();
    for (int st = 128; st > 0; st >>= 1) {
        if (tid < st) red[tid] += red[tid + st];
        __syncthreads();
    }
    if (tid == 0) g_alpha = (float)(red[0] / 67108864.0) + 1e-8f;
}

__device__ __forceinline__ uint32_t pack4(float a, float b, float c, float d) {
    int ia = (int)rintf(a), ib = (int)rintf(b), ic = (int)rintf(c), id = (int)rintf(d);
    return (uint32_t)(ia & 0xFF) | ((uint32_t)(ib & 0xFF) << 8) |
           ((uint32_t)(ic & 0xFF) << 16) | ((uint32_t)(id & 0xFF) << 24);
}

// ternary quant of W -> s8
__global__ void k_quant_w(const float4* __restrict__ w) {
    size_t i = (size_t)blockIdx.x * 256 + threadIdx.x;   // 4 float4 = 16 els
    float inva = 1.0f / g_alpha;
    uint4 o;
    uint32_t* po = &o.x;
#pragma unroll
    for (int q = 0; q < 4; q++) {
        float4 v = w[i * 4 + q];
        po[q] = pack4(fminf(fmaxf(rintf(v.x * inva), -1.f), 1.f),
                      fminf(fmaxf(rintf(v.y * inva), -1.f), 1.f),
                      fminf(fmaxf(rintf(v.z * inva), -1.f), 1.f),
                      fminf(fmaxf(rintf(v.w * inva), -1.f), 1.f));
    }
    ((uint4*)g_wq)[i] = o;
}

// per-token absmax int8 quant
__global__ void k_quant_x(const float* __restrict__ x) {
    __shared__ float red[256];
    int tid = threadIdx.x;
    int row = blockIdx.x;
    const float4* xr = (const float4*)(x + (size_t)row * KDIM);
    float4 v[4];
    float mx = 0.0f;
#pragma unroll
    for (int q = 0; q < 4; q++) {
        v[q] = xr[tid * 4 + q];
        mx = fmaxf(mx, fmaxf(fmaxf(fabsf(v[q].x), fabsf(v[q].y)),
                             fmaxf(fabsf(v[q].z), fabsf(v[q].w))));
    }
    red[tid] = mx;
    __syncthreads();
    for (int st = 128; st > 0; st >>= 1) {
        if (tid < st) red[tid] = fmaxf(red[tid], red[tid + st]);
        __syncthreads();
    }
    float gamma = fmaxf(red[0], 1e-8f);
    if (tid == 0) g_gamma[row] = gamma;
    uint4 o;
    uint32_t* po = &o.x;
#pragma unroll
    for (int q = 0; q < 4; q++) {
        po[q] = pack4(v[q].x / gamma * 127.0f, v[q].y / gamma * 127.0f,
                      v[q].z / gamma * 127.0f, v[q].w / gamma * 127.0f);
    }
    ((uint4*)(g_xq + (size_t)row * KDIM))[tid] = o;
}

// ---------------- launch ----------------
extern "C" void kernel_launch(void* const* d_in, const int* in_sizes, int n_in,
                              void* d_out, int out_size) {
    const float* x = (const float*)d_in[0];
    const float* w = (const float*)d_in[1];
    if (n_in >= 2 && in_sizes[0] == NDIM * KDIM) {   // defensive order check
        w = (const float*)d_in[0];
        x = (const float*)d_in[1];
    }
    float* out = (float*)d_out;

    cudaFuncSetAttribute(k_gemm, cudaFuncAttributeMaxDynamicSharedMemorySize,
                         SM_TOTAL);

    k_wabs1<<<1024, 256>>>((const float4*)w);
    k_wabs2<<<1, 256>>>();
    k_quant_w<<<NDIM * KDIM / (1024 * 4), 256>>>((const float4*)w);
    k_quant_x<<<TOKENS, 256>>>(x);
    k_gemm<<<(TOKENS / BM) * (NDIM / BN), 256, SM_TOTAL>>>(out);
}

// round 5
// speedup vs baseline: 1.0001x; 1.0001x over previous
#include <cuda_runtime.h>
#include <cuda_bf16.h>
#include <cstdint>

// BitLinear via exact integer math on IMMA (mma.sync m16n8k32 s8):
//   xi = round(x/gamma*127) in [-127,127]  (s8, exact)
//   t  = clip(round(w/alpha),-1,1)         (s8 trit, exact)
//   out[m,n] = gamma[m]*alpha/127 * sum_k xi[m,k]*t[n,k]   (s32 accum, exact)
// R4: resubmit of R3 (infra failure, no kernel signal): 2 CTAs/SM (16 warps)
// to hide barrier/LDSM latency.

#define TOKENS 8192
#define KDIM   4096
#define NDIM   16384

// -------- scratch (device globals) --------
__device__ int8_t g_xq[(size_t)TOKENS * KDIM];   // 32 MB
__device__ int8_t g_wq[(size_t)NDIM * KDIM];     // 64 MB
__device__ float  g_gamma[TOKENS];
__device__ float  g_alpha;
__device__ double g_part[1024];

// ---------------- helpers ----------------
__device__ __forceinline__ uint32_t smem_u32(const void* p) {
    uint32_t a;
    asm("{ .reg .u64 t; cvta.to.shared.u64 t, %1; cvt.u32.u64 %0, t; }"
        : "=r"(a) : "l"(p));
    return a;
}

#define SWZ128(o) ((o) ^ (((o) >> 3) & 0x70))

__device__ __forceinline__ void cp_async16(uint32_t dst, const void* src) {
    asm volatile("cp.async.cg.shared.global [%0], [%1], 16;\n"
                 :: "r"(dst), "l"(src));
}
#define CP_COMMIT() asm volatile("cp.async.commit_group;\n" ::: "memory")
#define CP_WAIT(n)  asm volatile("cp.async.wait_group %0;\n" :: "n"(n) : "memory")

__device__ __forceinline__ void ldsm4(uint32_t& r0, uint32_t& r1, uint32_t& r2,
                                      uint32_t& r3, uint32_t addr) {
    asm volatile("ldmatrix.sync.aligned.m8n8.x4.shared.b16 {%0,%1,%2,%3}, [%4];"
                 : "=r"(r0), "=r"(r1), "=r"(r2), "=r"(r3) : "r"(addr));
}

__device__ __forceinline__ void imma(int* c, const uint32_t* a, const uint32_t* b) {
    asm volatile(
        "mma.sync.aligned.m16n8k32.row.col.s32.s8.s8.s32 "
        "{%0,%1,%2,%3}, {%4,%5,%6,%7}, {%8,%9}, {%0,%1,%2,%3};"
        : "+r"(c[0]), "+r"(c[1]), "+r"(c[2]), "+r"(c[3])
        : "r"(a[0]), "r"(a[1]), "r"(a[2]), "r"(a[3]), "r"(b[0]), "r"(b[1]));
}

// ---------------- GEMM config ----------------
#define BM 128
#define BN 128
#define BK 128
#define STAGES 3
#define KTILES (KDIM / BK)            // 32
#define A_STAGE (BM * BK)             // 16384 B
#define B_STAGE (BN * BK)             // 16384 B
#define SM_A_OFF 0
#define SM_B_OFF (STAGES * A_STAGE)   // 49152
#define SM_TOTAL (SM_B_OFF + STAGES * B_STAGE)   // 98304 (x2 CTAs = 192KB/SM)

// Load one (A,B) K-tile stage into swizzled SMEM (256 threads).
__device__ __forceinline__ void load_stage(uint32_t sb, int tid, int m0, int n0,
                                           int kt, int s) {
    const int8_t* abase = g_xq + (size_t)m0 * KDIM + (size_t)kt * BK;
    uint32_t asm_ = sb + SM_A_OFF + s * A_STAGE;
#pragma unroll
    for (int i = 0; i < 4; i++) {                 // 128 rows x 8 chunks(16B)
        int idx = tid + i * 256;
        int r = idx >> 3, ch = idx & 7;
        cp_async16(asm_ + SWZ128(r * 128 + ch * 16),
                   abase + (size_t)r * KDIM + ch * 16);
    }
    const int8_t* bbase = g_wq + (size_t)n0 * KDIM + (size_t)kt * BK;
    uint32_t bsm = sb + SM_B_OFF + s * B_STAGE;
#pragma unroll
    for (int i = 0; i < 4; i++) {
        int idx = tid + i * 256;
        int r = idx >> 3, ch = idx & 7;
        cp_async16(bsm + SWZ128(r * 128 + ch * 16),
                   bbase + (size_t)r * KDIM + ch * 16);
    }
}

__global__ void __launch_bounds__(256, 2) k_gemm(float* __restrict__ out) {
    extern __shared__ __align__(1024) char smem[];
    uint32_t sb = smem_u32(smem);
    int tid = threadIdx.x, wid = tid >> 5, lane = tid & 31;
    int wm = wid & 1, wn = wid >> 1;              // warp grid 2(m) x 4(n)

    // supertile swizzle for L2 reuse
    int bid = blockIdx.x;
    const int TN = NDIM / BN;                     // 128
    const int GRP = 8;
    int g  = bid / (GRP * TN);
    int pm = g * GRP + (bid % GRP);
    int pn = (bid % (GRP * TN)) / GRP;
    int m0 = pm * BM, n0 = pn * BN;

    int acc[4][4][4];                             // [m-frag][n-frag][4]
#pragma unroll
    for (int i = 0; i < 4; i++)
#pragma unroll
        for (int j = 0; j < 4; j++)
#pragma unroll
            for (int q = 0; q < 4; q++) acc[i][j][q] = 0;

    // prologue
#pragma unroll
    for (int s = 0; s < STAGES - 1; s++) {
        load_stage(sb, tid, m0, n0, s, s);
        CP_COMMIT();
    }

    int rlo = lane & 7, sel = lane >> 3;

#pragma unroll 1
    for (int kt = 0; kt < KTILES; kt++) {
        int s = kt % STAGES;
        CP_WAIT(STAGES - 2);
        __syncthreads();

        int kn = kt + STAGES - 1;
        if (kn < KTILES) load_stage(sb, tid, m0, n0, kn, kn % STAGES);
        CP_COMMIT();

        uint32_t a_s = sb + SM_A_OFF + s * A_STAGE;
        uint32_t b_s = sb + SM_B_OFF + s * B_STAGE;
#pragma unroll
        for (int ks = 0; ks < 4; ks++) {          // 4 x k32 per BK=128
            uint32_t af[4][4], bf[4][2];
            // A frags: rows wm*64 + i*16 + (sel&1)*8 + rlo, chunk ks*2+(sel>>1)
#pragma unroll
            for (int i = 0; i < 4; i++) {
                int row = wm * 64 + i * 16 + (sel & 1) * 8 + rlo;
                int ch  = ks * 2 + (sel >> 1);
                ldsm4(af[i][0], af[i][1], af[i][2], af[i][3],
                      a_s + SWZ128(row * 128 + ch * 16));
            }
            // B frag pairs: rows wn*32 + j2*16 + (sel>>1)*8 + rlo, chunk ks*2+(sel&1)
#pragma unroll
            for (int j2 = 0; j2 < 2; j2++) {
                int row = wn * 32 + j2 * 16 + (sel >> 1) * 8 + rlo;
                int ch  = ks * 2 + (sel & 1);
                ldsm4(bf[2 * j2][0], bf[2 * j2][1], bf[2 * j2 + 1][0],
                      bf[2 * j2 + 1][1], b_s + SWZ128(row * 128 + ch * 16));
            }
#pragma unroll
            for (int i = 0; i < 4; i++)
#pragma unroll
                for (int j = 0; j < 4; j++) imma(acc[i][j], af[i], bf[j]);
        }
    }

    // epilogue: out = acc * gamma[row]*alpha/127
    float aod = g_alpha * (1.0f / 127.0f);
    int qrow = lane >> 2, qcol = (lane & 3) * 2;
#pragma unroll
    for (int i = 0; i < 4; i++) {
        int r0 = m0 + wm * 64 + i * 16 + qrow;
        float s0 = g_gamma[r0] * aod;
        float s1 = g_gamma[r0 + 8] * aod;
        float* p0 = out + (size_t)r0 * NDIM + n0 + wn * 32 + qcol;
        float* p1 = p0 + (size_t)8 * NDIM;
#pragma unroll
        for (int j = 0; j < 4; j++) {
            float2 v0 = make_float2((float)acc[i][j][0] * s0,
                                    (float)acc[i][j][1] * s0);
            float2 v1 = make_float2((float)acc[i][j][2] * s1,
                                    (float)acc[i][j][3] * s1);
            *reinterpret_cast<float2*>(p0 + j * 8) = v0;
            *reinterpret_cast<float2*>(p1 + j * 8) = v1;
        }
    }
}

// ---------------- preprocessing ----------------

// deterministic 2-stage |w| mean (double accumulation)
__global__ void k_wabs1(const float4* __restrict__ w) {
    __shared__ double red[256];
    int tid = threadIdx.x;
    size_t base = (size_t)blockIdx.x * 16384;
    double s = 0.0;
    for (int i = tid; i < 16384; i += 256) {
        float4 v = w[base + i];
        s += (double)fabsf(v.x) + (double)fabsf(v.y) +
             (double)fabsf(v.z) + (double)fabsf(v.w);
    }
    red[tid] = s;
    __syncthreads();
    for (int st = 128; st > 0; st >>= 1) {
        if (tid < st) red[tid] += red[tid + st];
        __syncthreads();
    }
    if (tid == 0) g_part[blockIdx.x] = red[0];
}

__global__ void k_wabs2() {
    __shared__ double red[256];
    int tid = threadIdx.x;
    double s = g_part[tid] + g_part[tid + 256] + g_part[tid + 512] + g_part[tid + 768];
    red[tid] = s;
    __syncthreads();
    for (int st = 128; st > 0; st >>= 1) {
        if (tid < st) red[tid] += red[tid + st];
        __syncthreads();
    }
    if (tid == 0) g_alpha = (float)(red[0] / 67108864.0) + 1e-8f;
}

__device__ __forceinline__ uint32_t pack4(float a, float b, float c, float d) {
    int ia = (int)rintf(a), ib = (int)rintf(b), ic = (int)rintf(c), id = (int)rintf(d);
    return (uint32_t)(ia & 0xFF) | ((uint32_t)(ib & 0xFF) << 8) |
           ((uint32_t)(ic & 0xFF) << 16) | ((uint32_t)(id & 0xFF) << 24);
}

// ternary quant of W -> s8
__global__ void k_quant_w(const float4* __restrict__ w) {
    size_t i = (size_t)blockIdx.x * 256 + threadIdx.x;   // 4 float4 = 16 els
    float inva = 1.0f / g_alpha;
    uint4 o;
    uint32_t* po = &o.x;
#pragma unroll
    for (int q = 0; q < 4; q++) {
        float4 v = w[i * 4 + q];
        po[q] = pack4(fminf(fmaxf(rintf(v.x * inva), -1.f), 1.f),
                      fminf(fmaxf(rintf(v.y * inva), -1.f), 1.f),
                      fminf(fmaxf(rintf(v.z * inva), -1.f), 1.f),
                      fminf(fmaxf(rintf(v.w * inva), -1.f), 1.f));
    }
    ((uint4*)g_wq)[i] = o;
}

// per-token absmax int8 quant
__global__ void k_quant_x(const float* __restrict__ x) {
    __shared__ float red[256];
    int tid = threadIdx.x;
    int row = blockIdx.x;
    const float4* xr = (const float4*)(x + (size_t)row * KDIM);
    float4 v[4];
    float mx = 0.0f;
#pragma unroll
    for (int q = 0; q < 4; q++) {
        v[q] = xr[tid * 4 + q];
        mx = fmaxf(mx, fmaxf(fmaxf(fabsf(v[q].x), fabsf(v[q].y)),
                             fmaxf(fabsf(v[q].z), fabsf(v[q].w))));
    }
    red[tid] = mx;
    __syncthreads();
    for (int st = 128; st > 0; st >>= 1) {
        if (tid < st) red[tid] = fmaxf(red[tid], red[tid + st]);
        __syncthreads();
    }
    float gamma = fmaxf(red[0], 1e-8f);
    if (tid == 0) g_gamma[row] = gamma;
    uint4 o;
    uint32_t* po = &o.x;
#pragma unroll
    for (int q = 0; q < 4; q++) {
        po[q] = pack4(v[q].x / gamma * 127.0f, v[q].y / gamma * 127.0f,
                      v[q].z / gamma * 127.0f, v[q].w / gamma * 127.0f);
    }
    ((uint4*)(g_xq + (size_t)row * KDIM))[tid] = o;
}

// ---------------- launch ----------------
extern "C" void kernel_launch(void* const* d_in, const int* in_sizes, int n_in,
                              void* d_out, int out_size) {
    const float* x = (const float*)d_in[0];
    const float* w = (const float*)d_in[1];
    if (n_in >= 2 && in_sizes[0] == NDIM * KDIM) {   // defensive order check
        w = (const float*)d_in[0];
        x = (const float*)d_in[1];
    }
    float* out = (float*)d_out;

    cudaFuncSetAttribute(k_gemm, cudaFuncAttributeMaxDynamicSharedMemorySize,
                         SM_TOTAL);

    k_wabs1<<<1024, 256>>>((const float4*)w);
    k_wabs2<<<1, 256>>>();
    k_quant_w<<<NDIM * KDIM / (1024 * 4), 256>>>((const float4*)w);
    k_quant_x<<<TOKENS, 256>>>(x);
    k_gemm<<<(TOKENS / BM) * (NDIM / BN), 256, SM_TOTAL>>>(out);
}

// round 7
// speedup vs baseline: 2.8315x; 2.8313x over previous
#include <cuda_runtime.h>
#include <cuda_bf16.h>
#include <cstdint>

// BitLinear via exact integer math, engine switched to legacy bf16 HMMA
// (mma.sync.m16n8k16.f32.bf16.bf16.f32):
//   xi = round(x/gamma*127) in [-127,127]  -> exact in bf16
//   t  = clip(round(w/alpha),-1,1)         -> exact in bf16
//   f32 accumulation of integers < 2^24   -> exact
// R6: s8 mma.sync proved emulated (~256 MACs/cyc/SM, occupancy-invariant);
// testing whether bf16 HMMA is native on sm_103.

#define TOKENS 8192
#define KDIM   4096
#define NDIM   16384

// -------- scratch (device globals) --------
__device__ __nv_bfloat16 g_xq[(size_t)TOKENS * KDIM];   // 64 MB
__device__ __nv_bfloat16 g_wq[(size_t)NDIM * KDIM];     // 128 MB
__device__ float  g_gamma[TOKENS];
__device__ float  g_alpha;
__device__ double g_part[1024];

// ---------------- helpers ----------------
__device__ __forceinline__ uint32_t smem_u32(const void* p) {
    uint32_t a;
    asm("{ .reg .u64 t; cvta.to.shared.u64 t, %1; cvt.u32.u64 %0, t; }"
        : "=r"(a) : "l"(p));
    return a;
}

#define SWZ128(o) ((o) ^ (((o) >> 3) & 0x70))

__device__ __forceinline__ void cp_async16(uint32_t dst, const void* src) {
    asm volatile("cp.async.cg.shared.global [%0], [%1], 16;\n"
                 :: "r"(dst), "l"(src));
}
#define CP_COMMIT() asm volatile("cp.async.commit_group;\n" ::: "memory")
#define CP_WAIT(n)  asm volatile("cp.async.wait_group %0;\n" :: "n"(n) : "memory")

__device__ __forceinline__ void ldsm4(uint32_t& r0, uint32_t& r1, uint32_t& r2,
                                      uint32_t& r3, uint32_t addr) {
    asm volatile("ldmatrix.sync.aligned.m8n8.x4.shared.b16 {%0,%1,%2,%3}, [%4];"
                 : "=r"(r0), "=r"(r1), "=r"(r2), "=r"(r3) : "r"(addr));
}

__device__ __forceinline__ void hmma(float* c, const uint32_t* a, const uint32_t* b) {
    asm volatile(
        "mma.sync.aligned.m16n8k16.row.col.f32.bf16.bf16.f32 "
        "{%0,%1,%2,%3}, {%4,%5,%6,%7}, {%8,%9}, {%0,%1,%2,%3};"
        : "+f"(c[0]), "+f"(c[1]), "+f"(c[2]), "+f"(c[3])
        : "r"(a[0]), "r"(a[1]), "r"(a[2]), "r"(a[3]), "r"(b[0]), "r"(b[1]));
}

// ---------------- GEMM config ----------------
#define BM 128
#define BN 128
#define BK 64                          // 64 bf16 = 128B rows
#define STAGES 3
#define KTILES (KDIM / BK)             // 64
#define A_STAGE (BM * 128)             // 16384 B
#define B_STAGE (BN * 128)             // 16384 B
#define SM_A_OFF 0
#define SM_B_OFF (STAGES * A_STAGE)    // 49152
#define SM_TOTAL (SM_B_OFF + STAGES * B_STAGE)   // 98304 (x2 CTAs = 192KB/SM)

// Load one (A,B) K-tile stage into swizzled SMEM (256 threads).
__device__ __forceinline__ void load_stage(uint32_t sb, int tid, int m0, int n0,
                                           int kt, int s) {
    const char* abase = (const char*)g_xq + ((size_t)m0 * KDIM + (size_t)kt * BK) * 2;
    uint32_t asm_ = sb + SM_A_OFF + s * A_STAGE;
#pragma unroll
    for (int i = 0; i < 4; i++) {                 // 128 rows x 8 chunks(16B)
        int idx = tid + i * 256;
        int r = idx >> 3, ch = idx & 7;
        cp_async16(asm_ + SWZ128(r * 128 + ch * 16),
                   abase + (size_t)r * (KDIM * 2) + ch * 16);
    }
    const char* bbase = (const char*)g_wq + ((size_t)n0 * KDIM + (size_t)kt * BK) * 2;
    uint32_t bsm = sb + SM_B_OFF + s * B_STAGE;
#pragma unroll
    for (int i = 0; i < 4; i++) {
        int idx = tid + i * 256;
        int r = idx >> 3, ch = idx & 7;
        cp_async16(bsm + SWZ128(r * 128 + ch * 16),
                   bbase + (size_t)r * (KDIM * 2) + ch * 16);
    }
}

__global__ void __launch_bounds__(256, 2) k_gemm(float* __restrict__ out) {
    extern __shared__ __align__(1024) char smem[];
    uint32_t sb = smem_u32(smem);
    int tid = threadIdx.x, wid = tid >> 5, lane = tid & 31;
    int wm = wid & 1, wn = wid >> 1;              // warp grid 2(m) x 4(n)

    // supertile swizzle for L2 reuse
    int bid = blockIdx.x;
    const int TN = NDIM / BN;                     // 128
    const int GRP = 8;
    int g  = bid / (GRP * TN);
    int pm = g * GRP + (bid % GRP);
    int pn = (bid % (GRP * TN)) / GRP;
    int m0 = pm * BM, n0 = pn * BN;

    float acc[4][4][4];                           // [m-frag][n-frag][4]
#pragma unroll
    for (int i = 0; i < 4; i++)
#pragma unroll
        for (int j = 0; j < 4; j++)
#pragma unroll
            for (int q = 0; q < 4; q++) acc[i][j][q] = 0.0f;

    // prologue
#pragma unroll
    for (int s = 0; s < STAGES - 1; s++) {
        load_stage(sb, tid, m0, n0, s, s);
        CP_COMMIT();
    }

    int rlo = lane & 7, sel = lane >> 3;

#pragma unroll 1
    for (int kt = 0; kt < KTILES; kt++) {
        int s = kt % STAGES;
        CP_WAIT(STAGES - 2);
        __syncthreads();

        int kn = kt + STAGES - 1;
        if (kn < KTILES) load_stage(sb, tid, m0, n0, kn, kn % STAGES);
        CP_COMMIT();

        uint32_t a_s = sb + SM_A_OFF + s * A_STAGE;
        uint32_t b_s = sb + SM_B_OFF + s * B_STAGE;
#pragma unroll
        for (int ks = 0; ks < 4; ks++) {          // 4 x k16 per BK=64
            uint32_t af[4][4], bf[4][2];
            // A frags: rows wm*64 + i*16 + (sel&1)*8 + rlo, 16B-chunk ks*2+(sel>>1)
#pragma unroll
            for (int i = 0; i < 4; i++) {
                int row = wm * 64 + i * 16 + (sel & 1) * 8 + rlo;
                int ch  = ks * 2 + (sel >> 1);
                ldsm4(af[i][0], af[i][1], af[i][2], af[i][3],
                      a_s + SWZ128(row * 128 + ch * 16));
            }
            // B frag pairs: rows wn*32 + j2*16 + (sel>>1)*8 + rlo, chunk ks*2+(sel&1)
#pragma unroll
            for (int j2 = 0; j2 < 2; j2++) {
                int row = wn * 32 + j2 * 16 + (sel >> 1) * 8 + rlo;
                int ch  = ks * 2 + (sel & 1);
                ldsm4(bf[2 * j2][0], bf[2 * j2][1], bf[2 * j2 + 1][0],
                      bf[2 * j2 + 1][1], b_s + SWZ128(row * 128 + ch * 16));
            }
#pragma unroll
            for (int i = 0; i < 4; i++)
#pragma unroll
                for (int j = 0; j < 4; j++) hmma(acc[i][j], af[i], bf[j]);
        }
    }

    // epilogue: out = acc * gamma[row]*alpha/127
    float aod = g_alpha * (1.0f / 127.0f);
    int qrow = lane >> 2, qcol = (lane & 3) * 2;
#pragma unroll
    for (int i = 0; i < 4; i++) {
        int r0 = m0 + wm * 64 + i * 16 + qrow;
        float s0 = g_gamma[r0] * aod;
        float s1 = g_gamma[r0 + 8] * aod;
        float* p0 = out + (size_t)r0 * NDIM + n0 + wn * 32 + qcol;
        float* p1 = p0 + (size_t)8 * NDIM;
#pragma unroll
        for (int j = 0; j < 4; j++) {
            float2 v0 = make_float2(acc[i][j][0] * s0, acc[i][j][1] * s0);
            float2 v1 = make_float2(acc[i][j][2] * s1, acc[i][j][3] * s1);
            *reinterpret_cast<float2*>(p0 + j * 8) = v0;
            *reinterpret_cast<float2*>(p1 + j * 8) = v1;
        }
    }
}

// ---------------- preprocessing ----------------

// deterministic 2-stage |w| mean (double accumulation)
__global__ void k_wabs1(const float4* __restrict__ w) {
    __shared__ double red[256];
    int tid = threadIdx.x;
    size_t base = (size_t)blockIdx.x * 16384;
    double s = 0.0;
    for (int i = tid; i < 16384; i += 256) {
        float4 v = w[base + i];
        s += (double)fabsf(v.x) + (double)fabsf(v.y) +
             (double)fabsf(v.z) + (double)fabsf(v.w);
    }
    red[tid] = s;
    __syncthreads();
    for (int st = 128; st > 0; st >>= 1) {
        if (tid < st) red[tid] += red[tid + st];
        __syncthreads();
    }
    if (tid == 0) g_part[blockIdx.x] = red[0];
}

__global__ void k_wabs2() {
    __shared__ double red[256];
    int tid = threadIdx.x;
    double s = g_part[tid] + g_part[tid + 256] + g_part[tid + 512] + g_part[tid + 768];
    red[tid] = s;
    __syncthreads();
    for (int st = 128; st > 0; st >>= 1) {
        if (tid < st) red[tid] += red[tid + st];
        __syncthreads();
    }
    if (tid == 0) g_alpha = (float)(red[0] / 67108864.0) + 1e-8f;
}

__device__ __forceinline__ unsigned pack_bf2(float a, float b) {
    unsigned short ua = __bfloat16_as_ushort(__float2bfloat16(a));
    unsigned short ub = __bfloat16_as_ushort(__float2bfloat16(b));
    return (unsigned)ua | ((unsigned)ub << 16);
}

// fused quant: blocks [0, NWB) quantize W (ternary->bf16),
//              blocks [NWB, NWB+TOKENS) quantize one x row each (int8->bf16)
#define NWB (NDIM * KDIM / (256 * 16))   // 16384 blocks, 16 els/thread
__global__ void k_quant(const float4* __restrict__ w, const float* __restrict__ x) {
    int bid = blockIdx.x;
    int tid = threadIdx.x;
    if (bid < NWB) {
        size_t i = (size_t)bid * 256 + tid;        // index of 16-element group
        float inva = 1.0f / g_alpha;
        uint4 o0, o1;
        uint32_t* po = &o0.x;
#pragma unroll
        for (int q = 0; q < 4; q++) {
            float4 v = w[i * 4 + q];
            float q0 = fminf(fmaxf(rintf(v.x * inva), -1.f), 1.f);
            float q1 = fminf(fmaxf(rintf(v.y * inva), -1.f), 1.f);
            float q2 = fminf(fmaxf(rintf(v.z * inva), -1.f), 1.f);
            float q3 = fminf(fmaxf(rintf(v.w * inva), -1.f), 1.f);
            if (q < 2) {
                po[q * 2]     = pack_bf2(q0, q1);
                po[q * 2 + 1] = pack_bf2(q2, q3);
            } else {
                (&o1.x)[(q - 2) * 2]     = pack_bf2(q0, q1);
                (&o1.x)[(q - 2) * 2 + 1] = pack_bf2(q2, q3);
            }
        }
        ((uint4*)g_wq)[i * 2]     = o0;
        ((uint4*)g_wq)[i * 2 + 1] = o1;
    } else {
        __shared__ float red[256];
        int row = bid - NWB;
        const float4* xr = (const float4*)(x + (size_t)row * KDIM);
        float4 v[4];
        float mx = 0.0f;
#pragma unroll
        for (int q = 0; q < 4; q++) {
            v[q] = xr[tid * 4 + q];
            mx = fmaxf(mx, fmaxf(fmaxf(fabsf(v[q].x), fabsf(v[q].y)),
                                 fmaxf(fabsf(v[q].z), fabsf(v[q].w))));
        }
        red[tid] = mx;
        __syncthreads();
        for (int st = 128; st > 0; st >>= 1) {
            if (tid < st) red[tid] = fmaxf(red[tid], red[tid + st]);
            __syncthreads();
        }
        float gamma = fmaxf(red[0], 1e-8f);
        if (tid == 0) g_gamma[row] = gamma;
        float isc = 127.0f / gamma;
        uint4 o0, o1;
#pragma unroll
        for (int q = 0; q < 4; q++) {
            float q0 = rintf(v[q].x * isc);
            float q1 = rintf(v[q].y * isc);
            float q2 = rintf(v[q].z * isc);
            float q3 = rintf(v[q].w * isc);
            uint32_t lo = pack_bf2(q0, q1), hi = pack_bf2(q2, q3);
            if (q < 2) { (&o0.x)[q * 2] = lo; (&o0.x)[q * 2 + 1] = hi; }
            else       { (&o1.x)[(q - 2) * 2] = lo; (&o1.x)[(q - 2) * 2 + 1] = hi; }
        }
        uint4* dst = (uint4*)(g_xq + (size_t)row * KDIM);
        dst[tid * 2]     = o0;
        dst[tid * 2 + 1] = o1;
    }
}

// ---------------- launch ----------------
extern "C" void kernel_launch(void* const* d_in, const int* in_sizes, int n_in,
                              void* d_out, int out_size) {
    const float* x = (const float*)d_in[0];
    const float* w = (const float*)d_in[1];
    if (n_in >= 2 && in_sizes[0] == NDIM * KDIM) {   // defensive order check
        w = (const float*)d_in[0];
        x = (const float*)d_in[1];
    }
    float* out = (float*)d_out;

    cudaFuncSetAttribute(k_gemm, cudaFuncAttributeMaxDynamicSharedMemorySize,
                         SM_TOTAL);

    k_wabs1<<<1024, 256>>>((const float4*)w);
    k_wabs2<<<1, 256>>>();
    k_quant<<<NWB + TOKENS, 256>>>((const float4*)w, x);
    k_gemm<<<(TOKENS / BM) * (NDIM / BN), 256, SM_TOTAL>>>(out);
}